// round 4
// baseline (speedup 1.0000x reference)
#include <cuda_runtime.h>
#include <math.h>

#define B_   128
#define S_   16
#define E_   512
#define E4   2048
#define R_   500
#define NIT  14

// ---------------- device scratch (static, no allocation) ----------------
__device__ float g_gate_emb[R_*E4];     // emb @ W_ih^T (NO bias), per relation row
__device__ float g_h1_emb  [R_*E_];
__device__ float g_gh_emb  [R_*E4];     // h1_emb @ W_hh^T
__device__ float g_krel    [R_*E_];     // emb @ W_k^T + b_k
__device__ float g_embT    [E_*E_];     // emb[:500]^T zero-padded to 512 cols
__device__ float g_gate_m  [B_*NIT*E4]; // merged-slot gate cache (NO bias)
__device__ float g_gh_m    [B_*NIT*E4];
__device__ float g_qk      [B_*1024];   // [q | k_last]
__device__ float g_scores  [B_*E_];     // raw q.k_rel dots (cols 0..499)
__device__ float g_prob    [B_*E_];     // softmax probs (cols 0..500, rest stays 0)
__device__ float g_merged  [B_*E_];
__device__ float g_h1new   [B_*E_];
__device__ float g_selh    [B_*E_];     // selected pair's h2
__device__ float g_blstm   [E4];
__device__ float g_wqk     [1024*E_];   // [fcq_w ; fck_w]
__device__ float g_bqk     [1024];
__device__ int   g_perm    [B_*S_];
__device__ int   g_sel     [B_];

__device__ __forceinline__ float* resolve(int id){
    switch(id){
        case 1:  return g_gate_emb;
        case 2:  return g_h1_emb;
        case 3:  return g_gh_emb;
        case 4:  return g_krel;
        case 5:  return g_embT;
        case 6:  return g_gate_m;
        case 7:  return g_gh_m;
        case 8:  return g_qk;
        case 9:  return g_scores;
        case 10: return g_prob;
        case 11: return g_merged;
        case 12: return g_h1new;
        case 13: return g_selh;
        case 14: return g_blstm;
        case 15: return g_wqk;
        case 16: return g_bqk;
        default: return nullptr;
    }
}

__device__ __forceinline__ float sigf(float x){ return 1.0f/(1.0f+expf(-x)); }

// Round fp32 -> TF32-representable fp32 (matches cuBLAS/XLA TF32 GEMM operand rounding)
__device__ __forceinline__ float tf32r(float x){
    float r;
    asm("cvt.rna.tf32.f32 %0, %1;" : "=f"(r) : "f"(x));
    return r;
}

// ---------------- generic NT GEMM (TF32 operands, fp32 accumulate) ----------------
// C[m][n] = sum_k tf32(A[m][k])*tf32(B[n][k]) (+bias fp32)
#define BM 64
#define BN 32
#define BK 16

__global__ void gemm_nt(const float* __restrict__ Aext, int Aid,
                        const float* __restrict__ Bext, int Bid,
                        const float* __restrict__ biasExt, int biasId,
                        int Cid, long long Coff,
                        int M, int N, int K,
                        int lda, int ldb, int ldc, int exFlag)
{
    const float* A    = Aext    ? Aext    : resolve(Aid);
    const float* Bm   = Bext    ? Bext    : resolve(Bid);
    const float* bias = biasExt ? biasExt : resolve(biasId);
    float* C = resolve(Cid) + Coff;

    __shared__ float As[BK][BM+4];
    __shared__ float Bs[BK][BN+4];

    int bm = blockIdx.y*BM, bn = blockIdx.x*BN;
    int tid = threadIdx.x;                 // 256 threads
    int arow = tid>>2,  ak = (tid&3)*4;    // A: 64 rows x (4 x float4)
    int brow = tid>>3,  bk = (tid&7)*2;    // B: 32 rows x (8 x float2)
    int ty = tid>>4, tx = tid&15;          // 16x16 thread grid, 4x2 per thread

    float acc[4][2] = {};

    for (int k0=0; k0<K; k0+=BK){
        float4 av = make_float4(0.f,0.f,0.f,0.f);
        if (bm+arow < M) av = *(const float4*)(A + (size_t)(bm+arow)*lda + k0 + ak);
        As[ak+0][arow]=tf32r(av.x); As[ak+1][arow]=tf32r(av.y);
        As[ak+2][arow]=tf32r(av.z); As[ak+3][arow]=tf32r(av.w);
        float2 bv = make_float2(0.f,0.f);
        if (bn+brow < N) bv = *(const float2*)(Bm + (size_t)(bn+brow)*ldb + k0 + bk);
        Bs[bk][brow]=tf32r(bv.x); Bs[bk+1][brow]=tf32r(bv.y);
        __syncthreads();
        #pragma unroll
        for (int k=0;k<BK;k++){
            float b0=Bs[k][tx*2+0], b1=Bs[k][tx*2+1];
            float a0=As[k][ty*4+0], a1=As[k][ty*4+1], a2=As[k][ty*4+2], a3=As[k][ty*4+3];
            acc[0][0]+=a0*b0; acc[0][1]+=a0*b1;
            acc[1][0]+=a1*b0; acc[1][1]+=a1*b1;
            acc[2][0]+=a2*b0; acc[2][1]+=a2*b1;
            acc[3][0]+=a3*b0; acc[3][1]+=a3*b1;
        }
        __syncthreads();
    }

    #pragma unroll
    for (int i=0;i<4;i++){
        int m = bm + ty*4 + i;
        if (m >= M) continue;
        #pragma unroll
        for (int j=0;j<2;j++){
            int n = bn + tx*2 + j;
            if (n >= N) continue;
            float v = acc[i][j];
            if (bias)   v += bias[n];
            if (exFlag) v += tf32r(g_prob[m*E_+500]) * tf32r(g_selh[m*E_+n]); // merged += p_last*sel_h
            C[(size_t)m*ldc + n] = v;
        }
    }
}

// ---------------- setup: b_lstm, stacked QK weights, emb^T (padded), perm, loss col 14 ----------------
__global__ void k_setup(const int* __restrict__ tokens,
                        const float* __restrict__ b_ih, const float* __restrict__ b_hh,
                        const float* __restrict__ fcq_w, const float* __restrict__ fcq_b,
                        const float* __restrict__ fck_w, const float* __restrict__ fck_b,
                        const float* __restrict__ emb, float* __restrict__ out)
{
    long long i = (long long)blockIdx.x*blockDim.x + threadIdx.x;
    if (i < E4){ g_blstm[i] = b_ih[i] + b_hh[i]; return; }
    i -= E4;
    if (i < (long long)1024*E_){
        int r = (int)(i / E_), k = (int)(i % E_);
        g_wqk[i] = (r < E_) ? fcq_w[r*E_+k] : fck_w[(r-E_)*E_+k];
        return;
    }
    i -= (long long)1024*E_;
    if (i < 1024){ g_bqk[i] = (i < E_) ? fcq_b[i] : fck_b[i-E_]; return; }
    i -= 1024;
    if (i < (long long)E_*E_){
        int e = (int)(i / E_), j = (int)(i % E_);
        g_embT[e*E_+j] = (j < R_) ? emb[(size_t)j*E_+e] : 0.0f;
        return;
    }
    i -= (long long)E_*E_;
    if (i < B_*S_){ g_perm[i] = tokens[i]; return; }
    i -= B_*S_;
    if (i < B_){ out[(size_t)B_*501 + i*16 + 14] = 0.0f; return; }
}

// ---------------- h1 from bias-free cached gates: gate = gx + b_lstm ----------------
__global__ void k_h1(int srcId, long long srcOff, int sstride, int dstId, int rows)
{
    const float* src = resolve(srcId) + srcOff;
    float* dst = resolve(dstId);
    int idx = blockIdx.x*blockDim.x + threadIdx.x;
    if (idx >= rows*E_) return;
    int r = idx / E_, e = idx % E_;
    const float* g = src + (size_t)r*sstride;
    float c1 = sigf(g[e] + g_blstm[e]) * tanhf(g[2*E_+e] + g_blstm[2*E_+e]);
    dst[r*E_+e] = sigf(g[3*E_+e] + g_blstm[3*E_+e]) * tanhf(c1);
}

// ---------------- per-batch pair scoring + argmax + selected h2 ----------------
__global__ void k_select(int len, const float* __restrict__ fc_w)
{
    int b = blockIdx.x;
    int tid = threadIdx.x;
    __shared__ float red[256];
    __shared__ float bestH[E_];
    __shared__ float s_best;
    __shared__ int   s_bestp;
    if (tid==0){ s_best = -3.0e38f; s_bestp = -1; }
    __syncthreads();

    int pairs = len - 1;
    const int* pm = g_perm + b*S_;
    const float* bl = g_blstm;
    for (int p=0; p<pairs; p++){
        int sa = pm[p], sb = pm[p+1];
        const float* gxa = (sa<R_) ? g_gate_emb + (size_t)sa*E4 : g_gate_m + ((size_t)b*NIT + (sa-R_))*E4;
        const float* gha = (sa<R_) ? g_gh_emb   + (size_t)sa*E4 : g_gh_m   + ((size_t)b*NIT + (sa-R_))*E4;
        const float* gxb = (sb<R_) ? g_gate_emb + (size_t)sb*E4 : g_gate_m + ((size_t)b*NIT + (sb-R_))*E4;

        float h2v[2]; float part = 0.0f;
        #pragma unroll
        for (int rr=0; rr<2; rr++){
            int e = tid + rr*256;
            // first cell (h=0): gate = gx_a + b
            float c1 = sigf(gxa[e] + bl[e]) * tanhf(gxa[2*E_+e] + bl[2*E_+e]);
            // second cell: gate = (gx_b + gh_a) + b   (matches reference add order)
            float i2 = (gxb[e      ] + gha[e      ]) + bl[e      ];
            float f2 = (gxb[E_  +e ] + gha[E_  +e ]) + bl[E_  +e ];
            float g2 = (gxb[2*E_+e ] + gha[2*E_+e ]) + bl[2*E_+e ];
            float o2 = (gxb[3*E_+e ] + gha[3*E_+e ]) + bl[3*E_+e ];
            float c2 = sigf(f2)*c1 + sigf(i2)*tanhf(g2);
            float h2 = sigf(o2)*tanhf(c2);
            h2v[rr] = h2;
            part += tf32r(h2) * tf32r(fc_w[e]);   // reference does h @ fc_w.T as a (TF32) dot
        }
        red[tid] = part; __syncthreads();
        for (int s=128; s>0; s>>=1){ if (tid < s) red[tid] += red[tid+s]; __syncthreads(); }
        if (tid==0){ if (red[0] > s_best){ s_best = red[0]; s_bestp = p; } }
        __syncthreads();
        if (s_bestp == p){ bestH[tid] = h2v[0]; bestH[tid+256] = h2v[1]; }
        __syncthreads();
    }
    g_selh[b*E_+tid]     = bestH[tid];
    g_selh[b*E_+tid+256] = bestH[tid+256];
    if (tid==0) g_sel[b] = s_bestp;
}

// ---------------- softmax + entropy (+ final output write) ----------------
__global__ void k_softmax(int it, int isFinal, float* __restrict__ out)
{
    int b = blockIdx.x, tid = threadIdx.x;
    __shared__ float sc[501];
    __shared__ float red[256];
    const float inv = 0.04419417382415922f;  // 1/sqrt(512)

    const float* q  = g_qk + b*1024;
    const float* kl = q + E_;
    float part = 0.0f;
    for (int e=tid; e<E_; e+=256) part += tf32r(q[e])*tf32r(kl[e]);
    red[tid]=part; __syncthreads();
    for (int s=128; s>0; s>>=1){ if (tid<s) red[tid]+=red[tid+s]; __syncthreads(); }
    if (tid==0) sc[500] = red[0]*inv;
    for (int j=tid; j<500; j+=256) sc[j] = g_scores[b*E_+j]*inv;
    __syncthreads();

    float m = -3.0e38f;
    for (int j=tid; j<501; j+=256) m = fmaxf(m, sc[j]);
    red[tid]=m; __syncthreads();
    for (int s=128; s>0; s>>=1){ if (tid<s) red[tid]=fmaxf(red[tid],red[tid+s]); __syncthreads(); }
    m = red[0]; __syncthreads();

    float zs=0.0f, ps=0.0f;
    for (int j=tid; j<501; j+=256){ float e_ = expf(sc[j]-m); zs += e_; ps += e_*sc[j]; }
    red[tid]=zs; __syncthreads();
    for (int s=128; s>0; s>>=1){ if (tid<s) red[tid]+=red[tid+s]; __syncthreads(); }
    float Z = red[0]; __syncthreads();
    red[tid]=ps; __syncthreads();
    for (int s=128; s>0; s>>=1){ if (tid<s) red[tid]+=red[tid+s]; __syncthreads(); }
    float P = red[0];

    float invZ = 1.0f/Z;
    for (int j=tid; j<501; j+=256) g_prob[b*E_+j] = expf(sc[j]-m)*invZ;

    if (tid==0){
        float ent = (m + logf(Z)) - P*invZ;
        out[(size_t)B_*501 + b*16 + (isFinal ? 15 : it)] = ent;
    }
    if (isFinal){
        for (int j=tid; j<501; j+=256) out[(size_t)b*501 + j] = sc[j];
    }
}

// ---------------- permutation update (merge at sel) ----------------
__global__ void k_update(int it, int len)
{
    int b = blockIdx.x*blockDim.x + threadIdx.x;
    if (b >= B_) return;
    int* pm = g_perm + b*S_;
    int sel = g_sel[b];
    for (int j=sel+1; j<len-1; j++) pm[j] = pm[j+1];
    pm[sel] = R_ + it;
}

// ---------------- host orchestration ----------------
static inline dim3 ggrid(int M, int N){ return dim3((N+BN-1)/BN, (M+BM-1)/BM); }

extern "C" void kernel_launch(void* const* d_in, const int* in_sizes, int n_in,
                              void* d_out, int out_size)
{
    const int*   tokens = (const int*)  d_in[0];
    const float* emb    = (const float*)d_in[1];
    const float* w_ih   = (const float*)d_in[2];
    const float* w_hh   = (const float*)d_in[3];
    const float* b_ih   = (const float*)d_in[4];
    const float* b_hh   = (const float*)d_in[5];
    const float* fc_w   = (const float*)d_in[6];
    /* fc_b (d_in[7]) not needed: sigmoid+const preserve argmax */
    const float* fcq_w  = (const float*)d_in[8];
    const float* fcq_b  = (const float*)d_in[9];
    const float* fck_w  = (const float*)d_in[10];
    const float* fck_b  = (const float*)d_in[11];
    float* out = (float*)d_out;

    // setup (blstm + wqk + bqk + embT + perm + loss col14)
    {
        long long total = (long long)E4 + (long long)1024*E_ + 1024 + (long long)E_*E_ + B_*S_ + B_;
        int blocks = (int)((total + 255)/256);
        k_setup<<<blocks,256>>>(tokens, b_ih, b_hh, fcq_w, fcq_b, fck_w, fck_b, emb, out);
    }
    // precompute tables (gate tables WITHOUT bias; bias added at use, ref order)
    gemm_nt<<<ggrid(R_,E4),256>>>(emb,0,  w_ih,0, nullptr,0, 1,0, R_,E4,E_, E_,E_,E4, 0);
    k_h1<<<(R_*E_+255)/256,256>>>(1,0,E4, 2, R_);
    gemm_nt<<<ggrid(R_,E4),256>>>(nullptr,2, w_hh,0, nullptr,0, 3,0, R_,E4,E_, E_,E_,E4, 0);
    gemm_nt<<<ggrid(R_,E_),256>>>(emb,0,  fck_w,0, fck_b,0, 4,0, R_,E_,E_, E_,E_,E_, 0);

    for (int it=0; it<NIT; ++it){
        int len = S_ - it;
        k_select<<<B_,256>>>(len, fc_w);
        // q|k_last = selh @ [Wq;Wk]^T + [bq;bk]
        gemm_nt<<<ggrid(B_,1024),256>>>(nullptr,13, nullptr,15, nullptr,16, 8,0, B_,1024,E_, E_,E_,1024, 0);
        // scores (rel part)
        gemm_nt<<<ggrid(B_,R_),256>>>(nullptr,8, nullptr,4, nullptr,0, 9,0, B_,R_,E_, 1024,E_,E_, 0);
        k_softmax<<<B_,256>>>(it, 0, out);
        // merged = prob[:, :500] @ emb[:500]  (+ p_last * selh via exFlag)
        gemm_nt<<<ggrid(B_,E_),256>>>(nullptr,10, nullptr,5, nullptr,0, 11,0, B_,E_,E_, E_,E_,E_, 1);
        // new slot caches (NO bias in gate cache)
        gemm_nt<<<ggrid(B_,E4),256>>>(nullptr,11, w_ih,0, nullptr,0, 6,(long long)it*E4, B_,E4,E_, E_,E_,NIT*E4, 0);
        k_h1<<<(B_*E_+255)/256,256>>>(6,(long long)it*E4, NIT*E4, 12, B_);
        gemm_nt<<<ggrid(B_,E4),256>>>(nullptr,12, w_hh,0, nullptr,0, 7,(long long)it*E4, B_,E4,E_, E_,E_,NIT*E4, 0);
        k_update<<<1,128>>>(it, len);
    }

    // final: len==2 pair -> attention -> outputs
    k_select<<<B_,256>>>(2, fc_w);
    gemm_nt<<<ggrid(B_,1024),256>>>(nullptr,13, nullptr,15, nullptr,16, 8,0, B_,1024,E_, E_,E_,1024, 0);
    gemm_nt<<<ggrid(B_,R_),256>>>(nullptr,8, nullptr,4, nullptr,0, 9,0, B_,R_,E_, 1024,E_,E_, 0);
    k_softmax<<<B_,256>>>(0, 1, out);
}

// round 5
// speedup vs baseline: 1.0786x; 1.0786x over previous
#include <cuda_runtime.h>
#include <math.h>

#define B_   128
#define S_   16
#define E_   512
#define E4   2048
#define R_   500
#define NIT  14

// ---------------- device scratch (static, no allocation) ----------------
__device__ float g_gate_emb[R_*E4];     // emb @ W_ih^T (NO bias), per relation row
__device__ float g_h1_emb  [R_*E_];
__device__ float g_gh_emb  [R_*E4];     // h1_emb @ W_hh^T
__device__ float g_krel    [R_*E_];     // emb @ W_k^T + b_k
__device__ float g_embT    [E_*E_];     // emb[:500]^T zero-padded to 512 cols
__device__ float g_gate_m  [B_*NIT*E4]; // merged-slot gate cache (NO bias)
__device__ float g_gh_m    [B_*NIT*E4];
__device__ float g_qk      [B_*1024];   // [q | k_last]
__device__ float g_scores  [B_*E_];     // raw q.k_rel dots (cols 0..499)
__device__ float g_prob    [B_*E_];     // softmax probs (cols 0..500, rest stays 0)
__device__ float g_merged  [B_*E_];
__device__ float g_h1new   [B_*E_];
__device__ float g_selh    [B_*E_];     // selected pair's h2
__device__ float g_blstm   [E4];
__device__ float g_wqk     [1024*E_];   // [fcq_w ; fck_w]
__device__ float g_bqk     [1024];
__device__ int   g_perm    [B_*S_];
__device__ int   g_sel     [B_];

__device__ __forceinline__ float* resolve(int id){
    switch(id){
        case 1:  return g_gate_emb;
        case 2:  return g_h1_emb;
        case 3:  return g_gh_emb;
        case 4:  return g_krel;
        case 5:  return g_embT;
        case 6:  return g_gate_m;
        case 7:  return g_gh_m;
        case 8:  return g_qk;
        case 9:  return g_scores;
        case 10: return g_prob;
        case 11: return g_merged;
        case 12: return g_h1new;
        case 13: return g_selh;
        case 14: return g_blstm;
        case 15: return g_wqk;
        case 16: return g_bqk;
        default: return nullptr;
    }
}

__device__ __forceinline__ float sigf(float x){ return 1.0f/(1.0f+expf(-x)); }

// Round fp32 -> TF32-representable fp32 (matches cuBLAS/XLA TF32 GEMM operand rounding)
__device__ __forceinline__ float tf32r(float x){
    float r;
    asm("cvt.rna.tf32.f32 %0, %1;" : "=f"(r) : "f"(x));
    return r;
}

// ---------------- NT GEMM (TF32 operands, fp32 accumulate), double-buffered ----------------
// C[m][n] = sum_k tf32(A[m][k])*tf32(B[n][k]) (+bias fp32)
#define BM 32
#define BN 64
#define BK 16

__global__ void gemm_nt(const float* __restrict__ Aext, int Aid,
                        const float* __restrict__ Bext, int Bid,
                        const float* __restrict__ biasExt, int biasId,
                        int Cid, long long Coff,
                        int M, int N, int K,
                        int lda, int ldb, int ldc, int exFlag)
{
    const float* A    = Aext    ? Aext    : resolve(Aid);
    const float* Bm   = Bext    ? Bext    : resolve(Bid);
    const float* bias = biasExt ? biasExt : resolve(biasId);
    float* C = resolve(Cid) + Coff;

    __shared__ float As[2][BK][BM];   // transposed: As[k][m]
    __shared__ float Bs[2][BK][BN];   // transposed: Bs[k][n]

    int tid = threadIdx.x;                 // 256 threads
    int bm = blockIdx.y*BM, bn = blockIdx.x*BN;
    int tx = tid & 15, ty = tid >> 4;      // 16x16 grid; 2x4 outputs per thread

    int ar = tid >> 3, ak = (tid & 7)*2;   // A: 32 rows x (8 x float2)
    int br = tid >> 2, bk = (tid & 3)*4;   // B: 64 rows x (4 x float4)

    const float* Ap = A  + (size_t)(bm+ar)*lda + ak;
    const float* Bp = Bm + (size_t)(bn+br)*ldb + bk;
    bool aok = (bm+ar) < M;
    bool bok = (bn+br) < N;

    float2 a2 = aok ? *(const float2*)Ap : make_float2(0.f,0.f);
    float4 b4 = bok ? *(const float4*)Bp : make_float4(0.f,0.f,0.f,0.f);
    As[0][ak  ][ar] = tf32r(a2.x);
    As[0][ak+1][ar] = tf32r(a2.y);
    Bs[0][bk  ][br] = tf32r(b4.x);
    Bs[0][bk+1][br] = tf32r(b4.y);
    Bs[0][bk+2][br] = tf32r(b4.z);
    Bs[0][bk+3][br] = tf32r(b4.w);
    __syncthreads();

    float acc[2][4] = {};
    int nt = K / BK;
    for (int t=0; t<nt; t++){
        int cur = t & 1;
        if (t+1 < nt){
            a2 = aok ? *(const float2*)(Ap + (t+1)*BK) : make_float2(0.f,0.f);
            b4 = bok ? *(const float4*)(Bp + (t+1)*BK) : make_float4(0.f,0.f,0.f,0.f);
        }
        #pragma unroll
        for (int k=0;k<BK;k++){
            float2 af = *(const float2*)&As[cur][k][ty*2];
            float4 bf = *(const float4*)&Bs[cur][k][tx*4];
            acc[0][0]+=af.x*bf.x; acc[0][1]+=af.x*bf.y; acc[0][2]+=af.x*bf.z; acc[0][3]+=af.x*bf.w;
            acc[1][0]+=af.y*bf.x; acc[1][1]+=af.y*bf.y; acc[1][2]+=af.y*bf.z; acc[1][3]+=af.y*bf.w;
        }
        if (t+1 < nt){
            int nx = cur ^ 1;
            As[nx][ak  ][ar] = tf32r(a2.x);
            As[nx][ak+1][ar] = tf32r(a2.y);
            Bs[nx][bk  ][br] = tf32r(b4.x);
            Bs[nx][bk+1][br] = tf32r(b4.y);
            Bs[nx][bk+2][br] = tf32r(b4.z);
            Bs[nx][bk+3][br] = tf32r(b4.w);
            __syncthreads();
        }
    }

    #pragma unroll
    for (int i=0;i<2;i++){
        int m = bm + ty*2 + i;
        if (m >= M) continue;
        #pragma unroll
        for (int j=0;j<4;j++){
            int n = bn + tx*4 + j;
            if (n >= N) continue;
            float v = acc[i][j];
            if (bias)   v += bias[n];
            if (exFlag) v += tf32r(g_prob[m*E_+500]) * tf32r(g_selh[m*E_+n]); // merged += p_last*sel_h
            C[(size_t)m*ldc + n] = v;
        }
    }
}

// ---------------- setup: b_lstm, stacked QK weights, emb^T (padded), perm, loss col 14 ----------------
__global__ void k_setup(const int* __restrict__ tokens,
                        const float* __restrict__ b_ih, const float* __restrict__ b_hh,
                        const float* __restrict__ fcq_w, const float* __restrict__ fcq_b,
                        const float* __restrict__ fck_w, const float* __restrict__ fck_b,
                        const float* __restrict__ emb, float* __restrict__ out)
{
    long long i = (long long)blockIdx.x*blockDim.x + threadIdx.x;
    if (i < E4){ g_blstm[i] = b_ih[i] + b_hh[i]; return; }
    i -= E4;
    if (i < (long long)1024*E_){
        int r = (int)(i / E_), k = (int)(i % E_);
        g_wqk[i] = (r < E_) ? fcq_w[r*E_+k] : fck_w[(r-E_)*E_+k];
        return;
    }
    i -= (long long)1024*E_;
    if (i < 1024){ g_bqk[i] = (i < E_) ? fcq_b[i] : fck_b[i-E_]; return; }
    i -= 1024;
    if (i < (long long)E_*E_){
        int e = (int)(i / E_), j = (int)(i % E_);
        g_embT[e*E_+j] = (j < R_) ? emb[(size_t)j*E_+e] : 0.0f;
        return;
    }
    i -= (long long)E_*E_;
    if (i < B_*S_){ g_perm[i] = tokens[i]; return; }
    i -= B_*S_;
    if (i < B_){ out[(size_t)B_*501 + i*16 + 14] = 0.0f; return; }
}

// ---------------- h1 from bias-free cached gates: gate = gx + b_lstm ----------------
__global__ void k_h1(int srcId, long long srcOff, int sstride, int dstId, int rows)
{
    const float* src = resolve(srcId) + srcOff;
    float* dst = resolve(dstId);
    int idx = blockIdx.x*blockDim.x + threadIdx.x;
    if (idx >= rows*E_) return;
    int r = idx / E_, e = idx % E_;
    const float* g = src + (size_t)r*sstride;
    float c1 = sigf(g[e] + g_blstm[e]) * tanhf(g[2*E_+e] + g_blstm[2*E_+e]);
    dst[r*E_+e] = sigf(g[3*E_+e] + g_blstm[3*E_+e]) * tanhf(c1);
}

// ---------------- per-batch pair scoring + argmax + selected h2 (+ fused perm update) ----------------
__global__ void k_select(int len, const float* __restrict__ fc_w, int it, int doUpd)
{
    int b = blockIdx.x;
    int tid = threadIdx.x;
    __shared__ float red[256];
    __shared__ float bestH[E_];
    __shared__ float s_best;
    __shared__ int   s_bestp;
    if (tid==0){ s_best = -3.0e38f; s_bestp = -1; }
    __syncthreads();

    int pairs = len - 1;
    int* pm = g_perm + b*S_;
    const float* bl = g_blstm;
    for (int p=0; p<pairs; p++){
        int sa = pm[p], sb = pm[p+1];
        const float* gxa = (sa<R_) ? g_gate_emb + (size_t)sa*E4 : g_gate_m + ((size_t)b*NIT + (sa-R_))*E4;
        const float* gha = (sa<R_) ? g_gh_emb   + (size_t)sa*E4 : g_gh_m   + ((size_t)b*NIT + (sa-R_))*E4;
        const float* gxb = (sb<R_) ? g_gate_emb + (size_t)sb*E4 : g_gate_m + ((size_t)b*NIT + (sb-R_))*E4;

        float h2v[2]; float part = 0.0f;
        #pragma unroll
        for (int rr=0; rr<2; rr++){
            int e = tid + rr*256;
            // first cell (h=0): gate = gx_a + b
            float c1 = sigf(gxa[e] + bl[e]) * tanhf(gxa[2*E_+e] + bl[2*E_+e]);
            // second cell: gate = (gx_b + gh_a) + b   (matches reference add order)
            float i2 = (gxb[e      ] + gha[e      ]) + bl[e      ];
            float f2 = (gxb[E_  +e ] + gha[E_  +e ]) + bl[E_  +e ];
            float g2 = (gxb[2*E_+e ] + gha[2*E_+e ]) + bl[2*E_+e ];
            float o2 = (gxb[3*E_+e ] + gha[3*E_+e ]) + bl[3*E_+e ];
            float c2 = sigf(f2)*c1 + sigf(i2)*tanhf(g2);
            float h2 = sigf(o2)*tanhf(c2);
            h2v[rr] = h2;
            part += tf32r(h2) * tf32r(fc_w[e]);   // reference does h @ fc_w.T as a (TF32) dot
        }
        red[tid] = part; __syncthreads();
        for (int s=128; s>0; s>>=1){ if (tid < s) red[tid] += red[tid+s]; __syncthreads(); }
        if (tid==0){ if (red[0] > s_best){ s_best = red[0]; s_bestp = p; } }
        __syncthreads();
        if (s_bestp == p){ bestH[tid] = h2v[0]; bestH[tid+256] = h2v[1]; }
        __syncthreads();
    }
    g_selh[b*E_+tid]     = bestH[tid];
    g_selh[b*E_+tid+256] = bestH[tid+256];
    if (tid==0){
        int sel = s_bestp;
        g_sel[b] = sel;
        if (doUpd){
            for (int j=sel+1; j<len-1; j++) pm[j] = pm[j+1];
            pm[sel] = R_ + it;
        }
    }
}

// ---------------- softmax + entropy (+ final output write) ----------------
__global__ void k_softmax(int it, int isFinal, float* __restrict__ out)
{
    int b = blockIdx.x, tid = threadIdx.x;
    __shared__ float sc[501];
    __shared__ float red[256];
    const float inv = 0.04419417382415922f;  // 1/sqrt(512)

    const float* q  = g_qk + b*1024;
    const float* kl = q + E_;
    float part = 0.0f;
    for (int e=tid; e<E_; e+=256) part += tf32r(q[e])*tf32r(kl[e]);
    red[tid]=part; __syncthreads();
    for (int s=128; s>0; s>>=1){ if (tid<s) red[tid]+=red[tid+s]; __syncthreads(); }
    if (tid==0) sc[500] = red[0]*inv;
    for (int j=tid; j<500; j+=256) sc[j] = g_scores[b*E_+j]*inv;
    __syncthreads();

    float m = -3.0e38f;
    for (int j=tid; j<501; j+=256) m = fmaxf(m, sc[j]);
    red[tid]=m; __syncthreads();
    for (int s=128; s>0; s>>=1){ if (tid<s) red[tid]=fmaxf(red[tid],red[tid+s]); __syncthreads(); }
    m = red[0]; __syncthreads();

    float zs=0.0f, ps=0.0f;
    for (int j=tid; j<501; j+=256){ float e_ = expf(sc[j]-m); zs += e_; ps += e_*sc[j]; }
    red[tid]=zs; __syncthreads();
    for (int s=128; s>0; s>>=1){ if (tid<s) red[tid]+=red[tid+s]; __syncthreads(); }
    float Z = red[0]; __syncthreads();
    red[tid]=ps; __syncthreads();
    for (int s=128; s>0; s>>=1){ if (tid<s) red[tid]+=red[tid+s]; __syncthreads(); }
    float P = red[0];

    float invZ = 1.0f/Z;
    for (int j=tid; j<501; j+=256) g_prob[b*E_+j] = expf(sc[j]-m)*invZ;

    if (tid==0){
        float ent = (m + logf(Z)) - P*invZ;
        out[(size_t)B_*501 + b*16 + (isFinal ? 15 : it)] = ent;
    }
    if (isFinal){
        for (int j=tid; j<501; j+=256) out[(size_t)b*501 + j] = sc[j];
    }
}

// ---------------- host orchestration ----------------
static inline dim3 ggrid(int M, int N){ return dim3((N+BN-1)/BN, (M+BM-1)/BM); }

extern "C" void kernel_launch(void* const* d_in, const int* in_sizes, int n_in,
                              void* d_out, int out_size)
{
    const int*   tokens = (const int*)  d_in[0];
    const float* emb    = (const float*)d_in[1];
    const float* w_ih   = (const float*)d_in[2];
    const float* w_hh   = (const float*)d_in[3];
    const float* b_ih   = (const float*)d_in[4];
    const float* b_hh   = (const float*)d_in[5];
    const float* fc_w   = (const float*)d_in[6];
    /* fc_b (d_in[7]) not needed: sigmoid+const preserve argmax */
    const float* fcq_w  = (const float*)d_in[8];
    const float* fcq_b  = (const float*)d_in[9];
    const float* fck_w  = (const float*)d_in[10];
    const float* fck_b  = (const float*)d_in[11];
    float* out = (float*)d_out;

    // setup (blstm + wqk + bqk + embT + perm + loss col14)
    {
        long long total = (long long)E4 + (long long)1024*E_ + 1024 + (long long)E_*E_ + B_*S_ + B_;
        int blocks = (int)((total + 255)/256);
        k_setup<<<blocks,256>>>(tokens, b_ih, b_hh, fcq_w, fcq_b, fck_w, fck_b, emb, out);
    }
    // precompute tables (gate tables WITHOUT bias; bias added at use, ref order)
    gemm_nt<<<ggrid(R_,E4),256>>>(emb,0,  w_ih,0, nullptr,0, 1,0, R_,E4,E_, E_,E_,E4, 0);
    k_h1<<<(R_*E_+255)/256,256>>>(1,0,E4, 2, R_);
    gemm_nt<<<ggrid(R_,E4),256>>>(nullptr,2, w_hh,0, nullptr,0, 3,0, R_,E4,E_, E_,E_,E4, 0);
    gemm_nt<<<ggrid(R_,E_),256>>>(emb,0,  fck_w,0, fck_b,0, 4,0, R_,E_,E_, E_,E_,E_, 0);

    for (int it=0; it<NIT; ++it){
        int len = S_ - it;
        k_select<<<B_,256>>>(len, fc_w, it, 1);
        // q|k_last = selh @ [Wq;Wk]^T + [bq;bk]
        gemm_nt<<<ggrid(B_,1024),256>>>(nullptr,13, nullptr,15, nullptr,16, 8,0, B_,1024,E_, E_,E_,1024, 0);
        // scores (rel part)
        gemm_nt<<<ggrid(B_,R_),256>>>(nullptr,8, nullptr,4, nullptr,0, 9,0, B_,R_,E_, 1024,E_,E_, 0);
        k_softmax<<<B_,256>>>(it, 0, out);
        // merged = prob[:, :500] @ emb[:500]  (+ p_last * selh via exFlag)
        gemm_nt<<<ggrid(B_,E_),256>>>(nullptr,10, nullptr,5, nullptr,0, 11,0, B_,E_,E_, E_,E_,E_, 1);
        // new slot caches (NO bias in gate cache)
        gemm_nt<<<ggrid(B_,E4),256>>>(nullptr,11, w_ih,0, nullptr,0, 6,(long long)it*E4, B_,E4,E_, E_,E_,NIT*E4, 0);
        k_h1<<<(B_*E_+255)/256,256>>>(6,(long long)it*E4, NIT*E4, 12, B_);
        gemm_nt<<<ggrid(B_,E4),256>>>(nullptr,12, w_hh,0, nullptr,0, 7,(long long)it*E4, B_,E4,E_, E_,E_,NIT*E4, 0);
    }

    // final: len==2 pair -> attention -> outputs
    k_select<<<B_,256>>>(2, fc_w, 0, 0);
    gemm_nt<<<ggrid(B_,1024),256>>>(nullptr,13, nullptr,15, nullptr,16, 8,0, B_,1024,E_, E_,E_,1024, 0);
    gemm_nt<<<ggrid(B_,R_),256>>>(nullptr,8, nullptr,4, nullptr,0, 9,0, B_,R_,E_, 1024,E_,E_, 0);
    k_softmax<<<B_,256>>>(0, 1, out);
}